// round 8
// baseline (speedup 1.0000x reference)
#include <cuda_runtime.h>
#include <math.h>

// Problem constants
#define T_    4
#define HH    256
#define WW    256
#define C_    256
#define PS_   8
#define NH_   8
#define HD_   32
#define NTOK  64
#define NWIN  4096
#define SCALE 0.1767766952966369f   // 1/sqrt(32)

// ---------------------------------------------------------------------------
// Scratch (__device__ globals: allocation-free rule)
// ---------------------------------------------------------------------------
__device__ float g_q[(size_t)NWIN * NH_ * NTOK * HD_];
__device__ float g_k[(size_t)NWIN * NH_ * NTOK * HD_];
__device__ float g_v[(size_t)NWIN * NH_ * NTOK * HD_];
__device__ float g_att[(size_t)NWIN * NTOK * C_];

// ---------------------------------------------------------------------------
// tf32 helpers
// ---------------------------------------------------------------------------
__device__ __forceinline__ float to_tf32(float x) {
    float r;
    asm("cvt.rna.tf32.f32 %0, %1;" : "=f"(r) : "f"(x));
    return r;
}

__device__ __forceinline__ void mma_tf32(float c[4],
                                         unsigned a0, unsigned a1, unsigned a2, unsigned a3,
                                         unsigned b0, unsigned b1) {
    asm volatile(
        "mma.sync.aligned.m16n8k8.row.col.f32.tf32.tf32.f32 "
        "{%0,%1,%2,%3}, {%4,%5,%6,%7}, {%8,%9}, {%0,%1,%2,%3};"
        : "+f"(c[0]), "+f"(c[1]), "+f"(c[2]), "+f"(c[3])
        : "r"(a0), "r"(a1), "r"(a2), "r"(a3), "r"(b0), "r"(b1));
}

// Tile geometry: block tile 128x128, 8 warps (2x4), warp tile 64x32, BK=32
#define BM 128
#define BN 128
#define BK 32
#define SA 36     // A smem row stride (floats)
#define SB 136    // B smem row stride (floats)

// ---------------------------------------------------------------------------
// Kernel 1: fused windowize + modulator + QKV GEMM (tf32 tensor cores)
//   grid (6, NWIN/2): block covers 2 windows (128 token rows) x 128 cols
// ---------------------------------------------------------------------------
__global__ __launch_bounds__(256)
void qkv_kernel(const float* __restrict__ vid, const float* __restrict__ mod,
                const float* __restrict__ wq,  const float* __restrict__ bq,
                const float* __restrict__ wkv, const float* __restrict__ bkv)
{
    __shared__ float As[BM * SA];
    __shared__ float Bs[BK * SB];

    const int w2  = blockIdx.y * 2;            // first of 2 windows
    const int jb0 = blockIdx.x * BN;
    const int t   = threadIdx.x;
    const int warp   = t >> 5;
    const int lane   = t & 31;
    const int grp    = lane >> 2;              // 0..7
    const int qid    = lane & 3;               // 0..3
    const int warp_m = warp >> 2;              // 0..1 (64-row half)
    const int warp_n = warp & 3;               // 0..3 (32-col strip)

    // ---- A loader geometry: row t>>1 (0..127), 16-float half-row
    const int arow  = t >> 1;
    const int acol0 = (t & 1) << 4;            // 0 or 16
    const int awin = w2 + (arow >> 6);
    const int an   = arow & 63;
    const int tf = awin >> 10, wh = (awin >> 5) & 31, wc = awin & 31;
    const int pi = an >> 3, pj = an & 7;
    const float* avid = vid + ((size_t)(tf * HH + wh * PS_ + pi) * WW
                               + wc * PS_ + pj) * C_ + acol0;
    const float* amod = mod + an * C_ + acol0;

    // ---- B loader geometry: row t>>3 (0..31) [K dim], cols (t&7)*4 + pass*32
    const int brow  = t >> 3;
    const int bcol0 = (t & 7) << 2;
    const float* bsrc; int ldb, jcol0;
    if (jb0 < C_) { bsrc = wq;  ldb = C_;     jcol0 = jb0; }
    else          { bsrc = wkv; ldb = 2 * C_; jcol0 = jb0 - C_; }
    const float* bptr = bsrc + (size_t)brow * ldb + jcol0 + bcol0;

    float4 aR[4], bR[4];
    // prefetch tile k0=0
    #pragma unroll
    for (int p = 0; p < 4; p++) {
        float4 va = *(const float4*)(avid + p * 4);
        float4 vm = *(const float4*)(amod + p * 4);
        aR[p].x = va.x + vm.x; aR[p].y = va.y + vm.y;
        aR[p].z = va.z + vm.z; aR[p].w = va.w + vm.w;
    }
    #pragma unroll
    for (int p = 0; p < 4; p++) bR[p] = *(const float4*)(bptr + p * 32);

    float acc[4][4][4];
    #pragma unroll
    for (int mt = 0; mt < 4; mt++)
        #pragma unroll
        for (int nt = 0; nt < 4; nt++)
            #pragma unroll
            for (int i = 0; i < 4; i++) acc[mt][nt][i] = 0.f;

    for (int k0 = 0; k0 < C_; k0 += BK) {
        // ---- stage registers -> smem (tf32-rounded) ----
        #pragma unroll
        for (int p = 0; p < 4; p++) {
            float* d = &As[arow * SA + acol0 + p * 4];
            d[0] = to_tf32(aR[p].x); d[1] = to_tf32(aR[p].y);
            d[2] = to_tf32(aR[p].z); d[3] = to_tf32(aR[p].w);
        }
        #pragma unroll
        for (int p = 0; p < 4; p++) {
            float* d = &Bs[brow * SB + bcol0 + p * 32];
            d[0] = to_tf32(bR[p].x); d[1] = to_tf32(bR[p].y);
            d[2] = to_tf32(bR[p].z); d[3] = to_tf32(bR[p].w);
        }
        __syncthreads();

        // ---- prefetch next tile while computing this one ----
        if (k0 + BK < C_) {
            #pragma unroll
            for (int p = 0; p < 4; p++) {
                float4 va = *(const float4*)(avid + k0 + BK + p * 4);
                float4 vm = *(const float4*)(amod + k0 + BK + p * 4);
                aR[p].x = va.x + vm.x; aR[p].y = va.y + vm.y;
                aR[p].z = va.z + vm.z; aR[p].w = va.w + vm.w;
            }
            // B advances along K = rows: stride ldb (fixed from R6 bug)
            #pragma unroll
            for (int p = 0; p < 4; p++)
                bR[p] = *(const float4*)(bptr + (size_t)(k0 + BK) * ldb + p * 32);
        }

        // ---- compute: 4 k8-steps, 16 MMAs each ----
        #pragma unroll
        for (int kk = 0; kk < BK; kk += 8) {
            unsigned a[4][4];
            #pragma unroll
            for (int mt = 0; mt < 4; mt++) {
                int rb = warp_m * 64 + mt * 16;
                a[mt][0] = __float_as_uint(As[(rb + grp    ) * SA + kk + qid    ]);
                a[mt][1] = __float_as_uint(As[(rb + grp + 8) * SA + kk + qid    ]);
                a[mt][2] = __float_as_uint(As[(rb + grp    ) * SA + kk + qid + 4]);
                a[mt][3] = __float_as_uint(As[(rb + grp + 8) * SA + kk + qid + 4]);
            }
            unsigned b[4][2];
            #pragma unroll
            for (int nt = 0; nt < 4; nt++) {
                int cb = warp_n * 32 + nt * 8;
                b[nt][0] = __float_as_uint(Bs[(kk + qid    ) * SB + cb + grp]);
                b[nt][1] = __float_as_uint(Bs[(kk + qid + 4) * SB + cb + grp]);
            }
            #pragma unroll
            for (int mt = 0; mt < 4; mt++)
                #pragma unroll
                for (int nt = 0; nt < 4; nt++)
                    mma_tf32(acc[mt][nt], a[mt][0], a[mt][1], a[mt][2], a[mt][3],
                             b[nt][0], b[nt][1]);
        }
        __syncthreads();
    }

    // ---- Epilogue: bias + scale + per-head scatter ----
    float* dst; int secoff; float mul;
    if (jb0 < C_)          { dst = g_q; secoff = 0;      mul = SCALE; }
    else if (jb0 < 2 * C_) { dst = g_k; secoff = C_;     mul = 1.f;   }
    else                   { dst = g_v; secoff = 2 * C_; mul = 1.f;   }

    #pragma unroll
    for (int nt = 0; nt < 4; nt++) {
        int col  = jb0 + warp_n * 32 + nt * 8 + 2 * qid;  // global QKV col
        int jloc = col - secoff;                           // 0..255 in section
        float b0, b1;
        if (jb0 < C_) { b0 = bq[col];       b1 = bq[col + 1]; }
        else          { b0 = bkv[col - C_]; b1 = bkv[col + 1 - C_]; }
        const int h = jloc >> 5;
        const int d = jloc & 31;
        #pragma unroll
        for (int mt = 0; mt < 4; mt++) {
            int m0   = warp_m * 64 + mt * 16 + grp;        // 16-tile never straddles 64
            int wloc = m0 >> 6;
            int nn   = m0 & 63;
            float* hp = dst + (((size_t)(w2 + wloc) * NH_ + h) * NTOK + nn) * HD_ + d;
            float2 o0 = { (acc[mt][nt][0] + b0) * mul, (acc[mt][nt][1] + b1) * mul };
            float2 o1 = { (acc[mt][nt][2] + b0) * mul, (acc[mt][nt][3] + b1) * mul };
            *(float2*)hp                       = o0;
            *(float2*)(hp + (size_t)8 * HD_)   = o1;
        }
    }
}

// ---------------------------------------------------------------------------
// Kernel 2: per-window attention (SIMT; unchanged)
// ---------------------------------------------------------------------------
__global__ __launch_bounds__(128)
void attn_kernel(const float* __restrict__ rpt)
{
    __shared__ float Ks[2][NTOK][HD_];
    __shared__ float Vs[2][NTOK][HD_];
    __shared__ float tb[2][225];

    const int w  = blockIdx.x;
    const int hl = threadIdx.x >> 6;
    const int n  = threadIdx.x & 63;
    const int h  = blockIdx.y * 2 + hl;

    const size_t base = ((size_t)w * NH_ + h) * NTOK * HD_;

    #pragma unroll
    for (int d4 = 0; d4 < HD_; d4 += 4) {
        *(float4*)&Ks[hl][n][d4] = *(const float4*)&g_k[base + n * HD_ + d4];
        *(float4*)&Vs[hl][n][d4] = *(const float4*)&g_v[base + n * HD_ + d4];
    }
    for (int i = n; i < 225; i += 64) tb[hl][i] = rpt[i * NH_ + h];

    float qr[HD_];
    #pragma unroll
    for (int d4 = 0; d4 < HD_; d4 += 4) {
        float4 q4 = *(const float4*)&g_q[base + n * HD_ + d4];
        qr[d4] = q4.x; qr[d4+1] = q4.y; qr[d4+2] = q4.z; qr[d4+3] = q4.w;
    }
    __syncthreads();

    const int qi = n >> 3, qj = n & 7;
    float s[NTOK];
    float mx = -1e30f;
    #pragma unroll
    for (int k = 0; k < NTOK; k++) {
        float dot = 0.f;
        #pragma unroll
        for (int d = 0; d < HD_; d++) dot += qr[d] * Ks[hl][k][d];
        const int ki = k >> 3, kj = k & 7;
        dot += tb[hl][(qi - ki + 7) * 15 + (qj - kj + 7)];
        s[k] = dot;
        mx = fmaxf(mx, dot);
    }
    float sum = 0.f;
    #pragma unroll
    for (int k = 0; k < NTOK; k++) { float e = __expf(s[k] - mx); s[k] = e; sum += e; }
    const float inv = 1.f / sum;

    float o[HD_];
    #pragma unroll
    for (int d = 0; d < HD_; d++) o[d] = 0.f;
    #pragma unroll
    for (int k = 0; k < NTOK; k++) {
        float wgt = s[k];
        #pragma unroll
        for (int d = 0; d < HD_; d++) o[d] += wgt * Vs[hl][k][d];
    }

    float* dstp = g_att + ((size_t)w * NTOK + n) * C_ + h * HD_;
    #pragma unroll
    for (int d4 = 0; d4 < HD_; d4 += 4) {
        float4 o4 = {o[d4] * inv, o[d4+1] * inv, o[d4+2] * inv, o[d4+3] * inv};
        *(float4*)&dstp[d4] = o4;
    }
}

// ---------------------------------------------------------------------------
// Kernel 3: output projection + un-windowize (tf32, same 128x128 structure)
//   grid (2, NWIN/2)
// ---------------------------------------------------------------------------
__global__ __launch_bounds__(256)
void proj_kernel(const float* __restrict__ pw, const float* __restrict__ pb,
                 float* __restrict__ out)
{
    __shared__ float As[BM * SA];
    __shared__ float Bs[BK * SB];

    const int w2  = blockIdx.y * 2;
    const int jb0 = blockIdx.x * BN;
    const int t   = threadIdx.x;
    const int warp   = t >> 5;
    const int lane   = t & 31;
    const int grp    = lane >> 2;
    const int qid    = lane & 3;
    const int warp_m = warp >> 2;
    const int warp_n = warp & 3;

    const int arow  = t >> 1;
    const int acol0 = (t & 1) << 4;
    // rows of 2 consecutive windows are contiguous in g_att
    const float* asrc = g_att + ((size_t)w2 * NTOK + arow) * C_ + acol0;

    const int brow  = t >> 3;
    const int bcol0 = (t & 7) << 2;
    const float* bptr = pw + (size_t)brow * C_ + jb0 + bcol0;

    float4 aR[4], bR[4];
    #pragma unroll
    for (int p = 0; p < 4; p++) aR[p] = *(const float4*)(asrc + p * 4);
    #pragma unroll
    for (int p = 0; p < 4; p++) bR[p] = *(const float4*)(bptr + p * 32);

    float acc[4][4][4];
    #pragma unroll
    for (int mt = 0; mt < 4; mt++)
        #pragma unroll
        for (int nt = 0; nt < 4; nt++)
            #pragma unroll
            for (int i = 0; i < 4; i++) acc[mt][nt][i] = 0.f;

    for (int k0 = 0; k0 < C_; k0 += BK) {
        #pragma unroll
        for (int p = 0; p < 4; p++) {
            float* d = &As[arow * SA + acol0 + p * 4];
            d[0] = to_tf32(aR[p].x); d[1] = to_tf32(aR[p].y);
            d[2] = to_tf32(aR[p].z); d[3] = to_tf32(aR[p].w);
        }
        #pragma unroll
        for (int p = 0; p < 4; p++) {
            float* d = &Bs[brow * SB + bcol0 + p * 32];
            d[0] = to_tf32(bR[p].x); d[1] = to_tf32(bR[p].y);
            d[2] = to_tf32(bR[p].z); d[3] = to_tf32(bR[p].w);
        }
        __syncthreads();

        if (k0 + BK < C_) {
            #pragma unroll
            for (int p = 0; p < 4; p++)
                aR[p] = *(const float4*)(asrc + k0 + BK + p * 4);
            // B advances along K = rows: stride C_ (fixed from R6 bug)
            #pragma unroll
            for (int p = 0; p < 4; p++)
                bR[p] = *(const float4*)(bptr + (size_t)(k0 + BK) * C_ + p * 32);
        }

        #pragma unroll
        for (int kk = 0; kk < BK; kk += 8) {
            unsigned a[4][4];
            #pragma unroll
            for (int mt = 0; mt < 4; mt++) {
                int rb = warp_m * 64 + mt * 16;
                a[mt][0] = __float_as_uint(As[(rb + grp    ) * SA + kk + qid    ]);
                a[mt][1] = __float_as_uint(As[(rb + grp + 8) * SA + kk + qid    ]);
                a[mt][2] = __float_as_uint(As[(rb + grp    ) * SA + kk + qid + 4]);
                a[mt][3] = __float_as_uint(As[(rb + grp + 8) * SA + kk + qid + 4]);
            }
            unsigned b[4][2];
            #pragma unroll
            for (int nt = 0; nt < 4; nt++) {
                int cb = warp_n * 32 + nt * 8;
                b[nt][0] = __float_as_uint(Bs[(kk + qid    ) * SB + cb + grp]);
                b[nt][1] = __float_as_uint(Bs[(kk + qid + 4) * SB + cb + grp]);
            }
            #pragma unroll
            for (int mt = 0; mt < 4; mt++)
                #pragma unroll
                for (int nt = 0; nt < 4; nt++)
                    mma_tf32(acc[mt][nt], a[mt][0], a[mt][1], a[mt][2], a[mt][3],
                             b[nt][0], b[nt][1]);
        }
        __syncthreads();
    }

    // ---- Epilogue: bias + spatial scatter ----
    #pragma unroll
    for (int nt = 0; nt < 4; nt++) {
        int col = jb0 + warp_n * 32 + nt * 8 + 2 * qid;
        float b0 = pb[col], b1 = pb[col + 1];
        #pragma unroll
        for (int mt = 0; mt < 4; mt++) {
            #pragma unroll
            for (int half = 0; half < 2; half++) {
                int m    = warp_m * 64 + mt * 16 + grp + half * 8;
                int wloc = m >> 6;
                int n    = m & 63;
                int win  = w2 + wloc;
                int tf = win >> 10, wh = (win >> 5) & 31, wc = win & 31;
                int pi = n >> 3, pj = n & 7;
                float* orow = out + ((size_t)(tf * HH + wh * PS_ + pi) * WW
                                     + wc * PS_ + pj) * C_;
                float2 o = { acc[mt][nt][half * 2 + 0] + b0,
                             acc[mt][nt][half * 2 + 1] + b1 };
                *(float2*)(orow + col) = o;
            }
        }
    }
}

// ---------------------------------------------------------------------------
extern "C" void kernel_launch(void* const* d_in, const int* in_sizes, int n_in,
                              void* d_out, int out_size)
{
    const float* vid  = (const float*)d_in[0];
    const float* mod  = (const float*)d_in[1];
    const float* wq   = (const float*)d_in[2];
    const float* bq   = (const float*)d_in[3];
    const float* wkv  = (const float*)d_in[4];
    const float* bkv  = (const float*)d_in[5];
    const float* pw   = (const float*)d_in[6];
    const float* pb   = (const float*)d_in[7];
    const float* rpt  = (const float*)d_in[8];
    float* out = (float*)d_out;

    dim3 g1(6, NWIN / 2);
    qkv_kernel<<<g1, 256>>>(vid, mod, wq, bq, wkv, bkv);

    dim3 g2(NWIN, NH_ / 2);
    attn_kernel<<<g2, 128>>>(rpt);

    dim3 g3(2, NWIN / 2);
    proj_kernel<<<g3, 256>>>(pw, pb, out);
}

// round 11
// speedup vs baseline: 1.2378x; 1.2378x over previous
#include <cuda_runtime.h>
#include <math.h>

// Problem constants
#define T_    4
#define HH    256
#define WW    256
#define C_    256
#define PS_   8
#define NH_   8
#define HD_   32
#define NTOK  64
#define NWIN  4096
#define SCALE 0.1767766952966369f   // 1/sqrt(32)

// ---------------------------------------------------------------------------
// Scratch (__device__ globals: allocation-free rule)
// ---------------------------------------------------------------------------
__device__ float g_q[(size_t)NWIN * NH_ * NTOK * HD_];
__device__ float g_k[(size_t)NWIN * NH_ * NTOK * HD_];
__device__ float g_v[(size_t)NWIN * NH_ * NTOK * HD_];
__device__ float g_att[(size_t)NWIN * NTOK * C_];

// ---------------------------------------------------------------------------
// tf32 helpers
// ---------------------------------------------------------------------------
__device__ __forceinline__ float to_tf32(float x) {
    float r;
    asm("cvt.rna.tf32.f32 %0, %1;" : "=f"(r) : "f"(x));
    return r;
}

__device__ __forceinline__ void mma_tf32(float c[4],
                                         unsigned a0, unsigned a1, unsigned a2, unsigned a3,
                                         unsigned b0, unsigned b1) {
    asm volatile(
        "mma.sync.aligned.m16n8k8.row.col.f32.tf32.tf32.f32 "
        "{%0,%1,%2,%3}, {%4,%5,%6,%7}, {%8,%9}, {%0,%1,%2,%3};"
        : "+f"(c[0]), "+f"(c[1]), "+f"(c[2]), "+f"(c[3])
        : "r"(a0), "r"(a1), "r"(a2), "r"(a3), "r"(b0), "r"(b1));
}

// Tile geometry: block tile 64x256, 8 warps (2x4), warp tile 32x64, BK=32
#define BM 64
#define BN 256
#define BK 32
#define SA 36     // A smem row stride: bank (4*grp+qid) -> conflict-free
#define SB 264    // B smem row stride: bank (8*qid+grp) -> conflict-free

// ---------------------------------------------------------------------------
// Kernel 1: fused windowize + modulator + QKV GEMM (tf32 tensor cores)
//   grid (3, NWIN): blockIdx.x = section (0=Q,1=K,2=V), one window per block
// ---------------------------------------------------------------------------
__global__ __launch_bounds__(256, 2)
void qkv_kernel(const float* __restrict__ vid, const float* __restrict__ mod,
                const float* __restrict__ wq,  const float* __restrict__ bq,
                const float* __restrict__ wkv, const float* __restrict__ bkv)
{
    __shared__ float As[BM * SA];   //  9.2 KB
    __shared__ float Bs[BK * SB];   // 33.8 KB

    const int sec = blockIdx.x;                // 0=Q, 1=K, 2=V
    const int w   = blockIdx.y;
    const int t   = threadIdx.x;
    const int warp   = t >> 5;
    const int lane   = t & 31;
    const int grp    = lane >> 2;              // 0..7
    const int qid    = lane & 3;               // 0..3
    const int warp_m = warp >> 2;              // 0..1 (32-row half)
    const int warp_n = warp & 3;               // 0..3 (64-col strip)

    // ---- A loader: row t>>2 (0..63), 8 consecutive floats at (t&3)*8
    const int arow  = t >> 2;
    const int acol0 = (t & 3) << 3;
    const int tf = w >> 10, wh = (w >> 5) & 31, wc = w & 31;
    const int pi = arow >> 3, pj = arow & 7;
    const float* avid = vid + ((size_t)(tf * HH + wh * PS_ + pi) * WW
                               + wc * PS_ + pj) * C_ + acol0;
    const float* amod = mod + arow * C_ + acol0;

    // ---- B loader: row t>>3 (0..31) [K dim], cols (t&7)*4 + p*32
    const int brow  = t >> 3;
    const int bcol0 = (t & 7) << 2;
    const int ldb   = (sec == 0) ? C_ : 2 * C_;
    const float* bptr = (sec == 0)
        ? wq  + (size_t)brow * C_ + bcol0
        : wkv + (size_t)brow * (2 * C_) + (sec == 2 ? C_ : 0) + bcol0;

    float acc[2][8][4];
    #pragma unroll
    for (int mt = 0; mt < 2; mt++)
        #pragma unroll
        for (int nt = 0; nt < 8; nt++)
            #pragma unroll
            for (int i = 0; i < 4; i++) acc[mt][nt][i] = 0.f;

    for (int k0 = 0; k0 < C_; k0 += BK) {
        // ---- A tile: vid + modulator, tf32-rounded ----
        #pragma unroll
        for (int p = 0; p < 2; p++) {
            float4 va = *(const float4*)(avid + k0 + p * 4);
            float4 vm = *(const float4*)(amod + k0 + p * 4);
            float* d = &As[arow * SA + acol0 + p * 4];
            d[0] = to_tf32(va.x + vm.x); d[1] = to_tf32(va.y + vm.y);
            d[2] = to_tf32(va.z + vm.z); d[3] = to_tf32(va.w + vm.w);
        }
        // ---- B tile: 8 float4 per thread (rows advance with ldb) ----
        #pragma unroll
        for (int p = 0; p < 8; p++) {
            float4 b4 = *(const float4*)(bptr + (size_t)k0 * ldb + p * 32);
            float* d = &Bs[brow * SB + bcol0 + p * 32];
            d[0] = to_tf32(b4.x); d[1] = to_tf32(b4.y);
            d[2] = to_tf32(b4.z); d[3] = to_tf32(b4.w);
        }
        __syncthreads();

        // ---- compute: 4 k8-steps, 16 MMAs each ----
        #pragma unroll
        for (int kk = 0; kk < BK; kk += 8) {
            unsigned a[2][4];
            #pragma unroll
            for (int mt = 0; mt < 2; mt++) {
                int rb = warp_m * 32 + mt * 16;
                a[mt][0] = __float_as_uint(As[(rb + grp    ) * SA + kk + qid    ]);
                a[mt][1] = __float_as_uint(As[(rb + grp + 8) * SA + kk + qid    ]);
                a[mt][2] = __float_as_uint(As[(rb + grp    ) * SA + kk + qid + 4]);
                a[mt][3] = __float_as_uint(As[(rb + grp + 8) * SA + kk + qid + 4]);
            }
            unsigned b[8][2];
            #pragma unroll
            for (int nt = 0; nt < 8; nt++) {
                int cb = warp_n * 64 + nt * 8;
                b[nt][0] = __float_as_uint(Bs[(kk + qid    ) * SB + cb + grp]);
                b[nt][1] = __float_as_uint(Bs[(kk + qid + 4) * SB + cb + grp]);
            }
            #pragma unroll
            for (int mt = 0; mt < 2; mt++)
                #pragma unroll
                for (int nt = 0; nt < 8; nt++)
                    mma_tf32(acc[mt][nt], a[mt][0], a[mt][1], a[mt][2], a[mt][3],
                             b[nt][0], b[nt][1]);
        }
        __syncthreads();
    }

    // ---- Epilogue: bias + scale + per-head scatter (whole section) ----
    float* dst = (sec == 0) ? g_q : (sec == 1) ? g_k : g_v;
    const float mul = (sec == 0) ? SCALE : 1.f;
    const float* bias = (sec == 0) ? bq : (sec == 2 ? bkv + C_ : bkv);

    #pragma unroll
    for (int nt = 0; nt < 8; nt++) {
        int col = warp_n * 64 + nt * 8 + 2 * qid;          // 0..255 in section
        float b0 = bias[col], b1 = bias[col + 1];
        const int h = col >> 5;
        const int d = col & 31;
        float* hp = dst + (((size_t)w * NH_ + h) * NTOK) * HD_ + d;
        #pragma unroll
        for (int mt = 0; mt < 2; mt++) {
            int m0 = warp_m * 32 + mt * 16 + grp;          // token row
            float2 o0 = { (acc[mt][nt][0] + b0) * mul, (acc[mt][nt][1] + b1) * mul };
            float2 o1 = { (acc[mt][nt][2] + b0) * mul, (acc[mt][nt][3] + b1) * mul };
            *(float2*)(hp + (size_t)m0 * HD_)       = o0;
            *(float2*)(hp + (size_t)(m0 + 8) * HD_) = o1;
        }
    }
}

// ---------------------------------------------------------------------------
// Kernel 2: per-window attention (SIMT; unchanged — known good)
// ---------------------------------------------------------------------------
__global__ __launch_bounds__(128)
void attn_kernel(const float* __restrict__ rpt)
{
    __shared__ float Ks[2][NTOK][HD_];
    __shared__ float Vs[2][NTOK][HD_];
    __shared__ float tb[2][225];

    const int w  = blockIdx.x;
    const int hl = threadIdx.x >> 6;
    const int n  = threadIdx.x & 63;
    const int h  = blockIdx.y * 2 + hl;

    const size_t base = ((size_t)w * NH_ + h) * NTOK * HD_;

    #pragma unroll
    for (int d4 = 0; d4 < HD_; d4 += 4) {
        *(float4*)&Ks[hl][n][d4] = *(const float4*)&g_k[base + n * HD_ + d4];
        *(float4*)&Vs[hl][n][d4] = *(const float4*)&g_v[base + n * HD_ + d4];
    }
    for (int i = n; i < 225; i += 64) tb[hl][i] = rpt[i * NH_ + h];

    float qr[HD_];
    #pragma unroll
    for (int d4 = 0; d4 < HD_; d4 += 4) {
        float4 q4 = *(const float4*)&g_q[base + n * HD_ + d4];
        qr[d4] = q4.x; qr[d4+1] = q4.y; qr[d4+2] = q4.z; qr[d4+3] = q4.w;
    }
    __syncthreads();

    const int qi = n >> 3, qj = n & 7;
    float s[NTOK];
    float mx = -1e30f;
    #pragma unroll
    for (int k = 0; k < NTOK; k++) {
        float dot = 0.f;
        #pragma unroll
        for (int d = 0; d < HD_; d++) dot += qr[d] * Ks[hl][k][d];
        const int ki = k >> 3, kj = k & 7;
        dot += tb[hl][(qi - ki + 7) * 15 + (qj - kj + 7)];
        s[k] = dot;
        mx = fmaxf(mx, dot);
    }
    float sum = 0.f;
    #pragma unroll
    for (int k = 0; k < NTOK; k++) { float e = __expf(s[k] - mx); s[k] = e; sum += e; }
    const float inv = 1.f / sum;

    float o[HD_];
    #pragma unroll
    for (int d = 0; d < HD_; d++) o[d] = 0.f;
    #pragma unroll
    for (int k = 0; k < NTOK; k++) {
        float wgt = s[k];
        #pragma unroll
        for (int d = 0; d < HD_; d++) o[d] += wgt * Vs[hl][k][d];
    }

    float* dstp = g_att + ((size_t)w * NTOK + n) * C_ + h * HD_;
    #pragma unroll
    for (int d4 = 0; d4 < HD_; d4 += 4) {
        float4 o4 = {o[d4] * inv, o[d4+1] * inv, o[d4+2] * inv, o[d4+3] * inv};
        *(float4*)&dstp[d4] = o4;
    }
}

// ---------------------------------------------------------------------------
// Kernel 3: output projection + un-windowize (tf32, 64x256 tile)
//   grid (NWIN): one window per block, all 256 output cols
// ---------------------------------------------------------------------------
__global__ __launch_bounds__(256, 2)
void proj_kernel(const float* __restrict__ pw, const float* __restrict__ pb,
                 float* __restrict__ out)
{
    __shared__ float As[BM * SA];
    __shared__ float Bs[BK * SB];

    const int w   = blockIdx.x;
    const int t   = threadIdx.x;
    const int warp   = t >> 5;
    const int lane   = t & 31;
    const int grp    = lane >> 2;
    const int qid    = lane & 3;
    const int warp_m = warp >> 2;
    const int warp_n = warp & 3;

    const int arow  = t >> 2;
    const int acol0 = (t & 3) << 3;
    const float* asrc = g_att + ((size_t)w * NTOK + arow) * C_ + acol0;

    const int brow  = t >> 3;
    const int bcol0 = (t & 7) << 2;
    const float* bptr = pw + (size_t)brow * C_ + bcol0;

    float acc[2][8][4];
    #pragma unroll
    for (int mt = 0; mt < 2; mt++)
        #pragma unroll
        for (int nt = 0; nt < 8; nt++)
            #pragma unroll
            for (int i = 0; i < 4; i++) acc[mt][nt][i] = 0.f;

    for (int k0 = 0; k0 < C_; k0 += BK) {
        #pragma unroll
        for (int p = 0; p < 2; p++) {
            float4 va = *(const float4*)(asrc + k0 + p * 4);
            float* d = &As[arow * SA + acol0 + p * 4];
            d[0] = to_tf32(va.x); d[1] = to_tf32(va.y);
            d[2] = to_tf32(va.z); d[3] = to_tf32(va.w);
        }
        #pragma unroll
        for (int p = 0; p < 8; p++) {
            float4 b4 = *(const float4*)(bptr + (size_t)k0 * C_ + p * 32);
            float* d = &Bs[brow * SB + bcol0 + p * 32];
            d[0] = to_tf32(b4.x); d[1] = to_tf32(b4.y);
            d[2] = to_tf32(b4.z); d[3] = to_tf32(b4.w);
        }
        __syncthreads();

        #pragma unroll
        for (int kk = 0; kk < BK; kk += 8) {
            unsigned a[2][4];
            #pragma unroll
            for (int mt = 0; mt < 2; mt++) {
                int rb = warp_m * 32 + mt * 16;
                a[mt][0] = __float_as_uint(As[(rb + grp    ) * SA + kk + qid    ]);
                a[mt][1] = __float_as_uint(As[(rb + grp + 8) * SA + kk + qid    ]);
                a[mt][2] = __float_as_uint(As[(rb + grp    ) * SA + kk + qid + 4]);
                a[mt][3] = __float_as_uint(As[(rb + grp + 8) * SA + kk + qid + 4]);
            }
            unsigned b[8][2];
            #pragma unroll
            for (int nt = 0; nt < 8; nt++) {
                int cb = warp_n * 64 + nt * 8;
                b[nt][0] = __float_as_uint(Bs[(kk + qid    ) * SB + cb + grp]);
                b[nt][1] = __float_as_uint(Bs[(kk + qid + 4) * SB + cb + grp]);
            }
            #pragma unroll
            for (int mt = 0; mt < 2; mt++)
                #pragma unroll
                for (int nt = 0; nt < 8; nt++)
                    mma_tf32(acc[mt][nt], a[mt][0], a[mt][1], a[mt][2], a[mt][3],
                             b[nt][0], b[nt][1]);
        }
        __syncthreads();
    }

    // ---- Epilogue: bias + spatial scatter ----
    const int tf = w >> 10, wh = (w >> 5) & 31, wc = w & 31;

    #pragma unroll
    for (int nt = 0; nt < 8; nt++) {
        int col = warp_n * 64 + nt * 8 + 2 * qid;
        float b0 = pb[col], b1 = pb[col + 1];
        #pragma unroll
        for (int mt = 0; mt < 2; mt++) {
            #pragma unroll
            for (int half = 0; half < 2; half++) {
                int m  = warp_m * 32 + mt * 16 + grp + half * 8;
                int pi = m >> 3, pj = m & 7;
                float* orow = out + ((size_t)(tf * HH + wh * PS_ + pi) * WW
                                     + wc * PS_ + pj) * C_;
                float2 o = { acc[mt][nt][half * 2 + 0] + b0,
                             acc[mt][nt][half * 2 + 1] + b1 };
                *(float2*)(orow + col) = o;
            }
        }
    }
}

// ---------------------------------------------------------------------------
extern "C" void kernel_launch(void* const* d_in, const int* in_sizes, int n_in,
                              void* d_out, int out_size)
{
    const float* vid  = (const float*)d_in[0];
    const float* mod  = (const float*)d_in[1];
    const float* wq   = (const float*)d_in[2];
    const float* bq   = (const float*)d_in[3];
    const float* wkv  = (const float*)d_in[4];
    const float* bkv  = (const float*)d_in[5];
    const float* pw   = (const float*)d_in[6];
    const float* pb   = (const float*)d_in[7];
    const float* rpt  = (const float*)d_in[8];
    float* out = (float*)d_out;

    dim3 g1(3, NWIN);
    qkv_kernel<<<g1, 256>>>(vid, mod, wq, bq, wkv, bkv);

    dim3 g2(NWIN, NH_ / 2);
    attn_kernel<<<g2, 128>>>(rpt);

    proj_kernel<<<NWIN, 256>>>(pw, pb, out);
}

// round 14
// speedup vs baseline: 1.3533x; 1.0934x over previous
#include <cuda_runtime.h>
#include <math.h>

// Problem constants
#define T_    4
#define HH    256
#define WW    256
#define C_    256
#define PS_   8
#define NH_   8
#define HD_   32
#define NTOK  64
#define NWIN  4096
#define SCALE 0.1767766952966369f   // 1/sqrt(32)

// ---------------------------------------------------------------------------
// Scratch (__device__ globals: allocation-free rule)
// ---------------------------------------------------------------------------
__device__ float g_q[(size_t)NWIN * NH_ * NTOK * HD_];
__device__ float g_k[(size_t)NWIN * NH_ * NTOK * HD_];
__device__ float g_v[(size_t)NWIN * NH_ * NTOK * HD_];
__device__ float g_att[(size_t)NWIN * NTOK * C_];
// pre-rounded (tf32) weights
__device__ float g_wq_t[C_ * C_];
__device__ float g_wkv_t[C_ * 2 * C_];
__device__ float g_pw_t[C_ * C_];

// ---------------------------------------------------------------------------
// helpers
// ---------------------------------------------------------------------------
__device__ __forceinline__ float to_tf32(float x) {
    float r;
    asm("cvt.rna.tf32.f32 %0, %1;" : "=f"(r) : "f"(x));
    return r;
}

__device__ __forceinline__ void mma_tf32(float c[4],
                                         unsigned a0, unsigned a1, unsigned a2, unsigned a3,
                                         unsigned b0, unsigned b1) {
    asm volatile(
        "mma.sync.aligned.m16n8k8.row.col.f32.tf32.tf32.f32 "
        "{%0,%1,%2,%3}, {%4,%5,%6,%7}, {%8,%9}, {%0,%1,%2,%3};"
        : "+f"(c[0]), "+f"(c[1]), "+f"(c[2]), "+f"(c[3])
        : "r"(a0), "r"(a1), "r"(a2), "r"(a3), "r"(b0), "r"(b1));
}

__device__ __forceinline__ void cp_async16(float* smem_dst, const float* gmem_src) {
    unsigned s = (unsigned)__cvta_generic_to_shared(smem_dst);
    asm volatile("cp.async.cg.shared.global [%0], [%1], 16;" :: "r"(s), "l"(gmem_src));
}
#define CP_COMMIT() asm volatile("cp.async.commit_group;")
#define CP_WAIT0()  asm volatile("cp.async.wait_group 0;")

// Tile geometry: block tile 64x256, 8 warps (2x4), warp tile 32x64, BK=32
#define BM 64
#define BN 256
#define BK 32
#define SA 36     // A smem row stride (floats); 36*4=144B = 9*16 -> 16B aligned rows
#define SB 264    // B smem row stride (floats); 264*4=1056B = 66*16
#define ASZ (BM * SA)
#define BSZ (BK * SB)
#define SMEM_GEMM (2 * (ASZ + BSZ) * sizeof(float))   // 84 KB

// ---------------------------------------------------------------------------
// Kernel 0: pre-round weights to tf32 (once per launch)
// ---------------------------------------------------------------------------
__global__ __launch_bounds__(256)
void prep_weights(const float* __restrict__ wq, const float* __restrict__ wkv,
                  const float* __restrict__ pw)
{
    int i = blockIdx.x * blockDim.x + threadIdx.x;     // 0 .. 131071
    if (i < C_ * C_) {
        g_wq_t[i] = to_tf32(wq[i]);
        g_pw_t[i] = to_tf32(pw[i]);
    }
    g_wkv_t[i] = to_tf32(wkv[i]);                      // 131072 elements
}

// ---------------------------------------------------------------------------
// Kernel 1: fused windowize + modulator + QKV GEMM (tf32, cp.async 2-stage)
//   grid (3, NWIN): blockIdx.x = section (0=Q,1=K,2=V), one window per block
// ---------------------------------------------------------------------------
__global__ __launch_bounds__(256, 2)
void qkv_kernel(const float* __restrict__ vid, const float* __restrict__ mod,
                const float* __restrict__ bq,  const float* __restrict__ bkv)
{
    extern __shared__ float sm[];
    float* Asb = sm;               // [2][ASZ]
    float* Bsb = sm + 2 * ASZ;     // [2][BSZ]

    const int sec = blockIdx.x;                // 0=Q, 1=K, 2=V
    const int w   = blockIdx.y;
    const int t   = threadIdx.x;
    const int warp   = t >> 5;
    const int lane   = t & 31;
    const int grp    = lane >> 2;
    const int qid    = lane & 3;
    const int warp_m = warp >> 2;              // 0..1
    const int warp_n = warp & 3;               // 0..3

    // ---- A loader: row t>>2 (0..63), 8 floats at (t&3)*8
    const int arow  = t >> 2;
    const int acol0 = (t & 3) << 3;
    const int tf = w >> 10, wh = (w >> 5) & 31, wc = w & 31;
    const int pi = arow >> 3, pj = arow & 7;
    const float* avid = vid + ((size_t)(tf * HH + wh * PS_ + pi) * WW
                               + wc * PS_ + pj) * C_ + acol0;
    const float* amod = mod + arow * C_ + acol0;

    // ---- B loader: row t>>3 (0..31), cols (t&7)*4 + p*32 (pre-rounded weights)
    const int brow  = t >> 3;
    const int bcol0 = (t & 7) << 2;
    const int ldb   = (sec == 0) ? C_ : 2 * C_;
    const float* bptr = (sec == 0)
        ? g_wq_t  + (size_t)brow * C_ + bcol0
        : g_wkv_t + (size_t)brow * (2 * C_) + (sec == 2 ? C_ : 0) + bcol0;

    // ---- prologue: tile 0 ----
    {
        float* Bw = Bsb;                        // buffer 0
        #pragma unroll
        for (int q = 0; q < 8; q++)
            cp_async16(&Bw[brow * SB + bcol0 + q * 32], bptr + q * 32);
        CP_COMMIT();
        float* Aw = Asb;
        #pragma unroll
        for (int q = 0; q < 2; q++) {
            float4 va = *(const float4*)(avid + q * 4);
            float4 vm = *(const float4*)(amod + q * 4);
            float* d = &Aw[arow * SA + acol0 + q * 4];
            d[0] = to_tf32(va.x + vm.x); d[1] = to_tf32(va.y + vm.y);
            d[2] = to_tf32(va.z + vm.z); d[3] = to_tf32(va.w + vm.w);
        }
    }

    float acc[2][8][4];
    #pragma unroll
    for (int mt = 0; mt < 2; mt++)
        #pragma unroll
        for (int nt = 0; nt < 8; nt++)
            #pragma unroll
            for (int i = 0; i < 4; i++) acc[mt][nt][i] = 0.f;

    int p = 0;
    for (int k0 = 0; k0 < C_; k0 += BK) {
        CP_WAIT0();
        __syncthreads();

        const int kn = k0 + BK;
        float4 aR[2];
        if (kn < C_) {
            // issue next B tile async into other buffer
            float* Bw = Bsb + (p ^ 1) * BSZ;
            #pragma unroll
            for (int q = 0; q < 8; q++)
                cp_async16(&Bw[brow * SB + bcol0 + q * 32],
                           bptr + (size_t)kn * ldb + q * 32);
            CP_COMMIT();
            // prefetch next A into registers (latency overlaps compute)
            #pragma unroll
            for (int q = 0; q < 2; q++) {
                float4 va = *(const float4*)(avid + kn + q * 4);
                float4 vm = *(const float4*)(amod + kn + q * 4);
                aR[q].x = va.x + vm.x; aR[q].y = va.y + vm.y;
                aR[q].z = va.z + vm.z; aR[q].w = va.w + vm.w;
            }
        }

        // ---- compute on buffer p ----
        const float* A_ = Asb + p * ASZ;
        const float* B_ = Bsb + p * BSZ;
        #pragma unroll
        for (int kk = 0; kk < BK; kk += 8) {
            unsigned a[2][4];
            #pragma unroll
            for (int mt = 0; mt < 2; mt++) {
                int rb = warp_m * 32 + mt * 16;
                a[mt][0] = __float_as_uint(A_[(rb + grp    ) * SA + kk + qid    ]);
                a[mt][1] = __float_as_uint(A_[(rb + grp + 8) * SA + kk + qid    ]);
                a[mt][2] = __float_as_uint(A_[(rb + grp    ) * SA + kk + qid + 4]);
                a[mt][3] = __float_as_uint(A_[(rb + grp + 8) * SA + kk + qid + 4]);
            }
            unsigned b[8][2];
            #pragma unroll
            for (int nt = 0; nt < 8; nt++) {
                int cb = warp_n * 64 + nt * 8;
                b[nt][0] = __float_as_uint(B_[(kk + qid    ) * SB + cb + grp]);
                b[nt][1] = __float_as_uint(B_[(kk + qid + 4) * SB + cb + grp]);
            }
            #pragma unroll
            for (int mt = 0; mt < 2; mt++)
                #pragma unroll
                for (int nt = 0; nt < 8; nt++)
                    mma_tf32(acc[mt][nt], a[mt][0], a[mt][1], a[mt][2], a[mt][3],
                             b[nt][0], b[nt][1]);
        }

        if (kn < C_) {
            float* Aw = Asb + (p ^ 1) * ASZ;
            #pragma unroll
            for (int q = 0; q < 2; q++) {
                float* d = &Aw[arow * SA + acol0 + q * 4];
                d[0] = to_tf32(aR[q].x); d[1] = to_tf32(aR[q].y);
                d[2] = to_tf32(aR[q].z); d[3] = to_tf32(aR[q].w);
            }
        }
        p ^= 1;
    }

    // ---- Epilogue: bias + scale + per-head scatter ----
    float* dst = (sec == 0) ? g_q : (sec == 1) ? g_k : g_v;
    const float mul = (sec == 0) ? SCALE : 1.f;
    const float* bias = (sec == 0) ? bq : (sec == 2 ? bkv + C_ : bkv);

    #pragma unroll
    for (int nt = 0; nt < 8; nt++) {
        int col = warp_n * 64 + nt * 8 + 2 * qid;
        float b0 = bias[col], b1 = bias[col + 1];
        const int h = col >> 5;
        const int d = col & 31;
        float* hp = dst + (((size_t)w * NH_ + h) * NTOK) * HD_ + d;
        #pragma unroll
        for (int mt = 0; mt < 2; mt++) {
            int m0 = warp_m * 32 + mt * 16 + grp;
            float2 o0 = { (acc[mt][nt][0] + b0) * mul, (acc[mt][nt][1] + b1) * mul };
            float2 o1 = { (acc[mt][nt][2] + b0) * mul, (acc[mt][nt][3] + b1) * mul };
            *(float2*)(hp + (size_t)m0 * HD_)       = o0;
            *(float2*)(hp + (size_t)(m0 + 8) * HD_) = o1;
        }
    }
}

// ---------------------------------------------------------------------------
// Kernel 2: per-window attention (SIMT; outputs tf32-rounded for proj cp.async)
// ---------------------------------------------------------------------------
__global__ __launch_bounds__(128)
void attn_kernel(const float* __restrict__ rpt)
{
    __shared__ float Ks[2][NTOK][HD_];
    __shared__ float Vs[2][NTOK][HD_];
    __shared__ float tb[2][225];

    const int w  = blockIdx.x;
    const int hl = threadIdx.x >> 6;
    const int n  = threadIdx.x & 63;
    const int h  = blockIdx.y * 2 + hl;

    const size_t base = ((size_t)w * NH_ + h) * NTOK * HD_;

    #pragma unroll
    for (int d4 = 0; d4 < HD_; d4 += 4) {
        *(float4*)&Ks[hl][n][d4] = *(const float4*)&g_k[base + n * HD_ + d4];
        *(float4*)&Vs[hl][n][d4] = *(const float4*)&g_v[base + n * HD_ + d4];
    }
    for (int i = n; i < 225; i += 64) tb[hl][i] = rpt[i * NH_ + h];

    float qr[HD_];
    #pragma unroll
    for (int d4 = 0; d4 < HD_; d4 += 4) {
        float4 q4 = *(const float4*)&g_q[base + n * HD_ + d4];
        qr[d4] = q4.x; qr[d4+1] = q4.y; qr[d4+2] = q4.z; qr[d4+3] = q4.w;
    }
    __syncthreads();

    const int qi = n >> 3, qj = n & 7;
    float s[NTOK];
    float mx = -1e30f;
    #pragma unroll
    for (int k = 0; k < NTOK; k++) {
        float dot = 0.f;
        #pragma unroll
        for (int d = 0; d < HD_; d++) dot += qr[d] * Ks[hl][k][d];
        const int ki = k >> 3, kj = k & 7;
        dot += tb[hl][(qi - ki + 7) * 15 + (qj - kj + 7)];
        s[k] = dot;
        mx = fmaxf(mx, dot);
    }
    float sum = 0.f;
    #pragma unroll
    for (int k = 0; k < NTOK; k++) { float e = __expf(s[k] - mx); s[k] = e; sum += e; }
    const float inv = 1.f / sum;

    float o[HD_];
    #pragma unroll
    for (int d = 0; d < HD_; d++) o[d] = 0.f;
    #pragma unroll
    for (int k = 0; k < NTOK; k++) {
        float wgt = s[k];
        #pragma unroll
        for (int d = 0; d < HD_; d++) o[d] += wgt * Vs[hl][k][d];
    }

    // store tf32-rounded so proj can cp.async its A tiles with no cvt
    float* dstp = g_att + ((size_t)w * NTOK + n) * C_ + h * HD_;
    #pragma unroll
    for (int d4 = 0; d4 < HD_; d4 += 4) {
        float4 o4 = { to_tf32(o[d4] * inv),   to_tf32(o[d4+1] * inv),
                      to_tf32(o[d4+2] * inv), to_tf32(o[d4+3] * inv) };
        *(float4*)&dstp[d4] = o4;
    }
}

// ---------------------------------------------------------------------------
// Kernel 3: output projection + un-windowize (tf32, cp.async both operands)
//   grid (NWIN): one window per block
// ---------------------------------------------------------------------------
__global__ __launch_bounds__(256, 2)
void proj_kernel(const float* __restrict__ pb, float* __restrict__ out)
{
    extern __shared__ float sm[];
    float* Asb = sm;
    float* Bsb = sm + 2 * ASZ;

    const int w   = blockIdx.x;
    const int t   = threadIdx.x;
    const int warp   = t >> 5;
    const int lane   = t & 31;
    const int grp    = lane >> 2;
    const int qid    = lane & 3;
    const int warp_m = warp >> 2;
    const int warp_n = warp & 3;

    const int arow  = t >> 2;
    const int acol0 = (t & 3) << 3;
    const float* asrc = g_att + ((size_t)w * NTOK + arow) * C_ + acol0;

    const int brow  = t >> 3;
    const int bcol0 = (t & 7) << 2;
    const float* bptr = g_pw_t + (size_t)brow * C_ + bcol0;

    // ---- prologue: tile 0 (both operands async) ----
    {
        float* Bw = Bsb;
        #pragma unroll
        for (int q = 0; q < 8; q++)
            cp_async16(&Bw[brow * SB + bcol0 + q * 32], bptr + q * 32);
        float* Aw = Asb;
        #pragma unroll
        for (int q = 0; q < 2; q++)
            cp_async16(&Aw[arow * SA + acol0 + q * 4], asrc + q * 4);
        CP_COMMIT();
    }

    float acc[2][8][4];
    #pragma unroll
    for (int mt = 0; mt < 2; mt++)
        #pragma unroll
        for (int nt = 0; nt < 8; nt++)
            #pragma unroll
            for (int i = 0; i < 4; i++) acc[mt][nt][i] = 0.f;

    int p = 0;
    for (int k0 = 0; k0 < C_; k0 += BK) {
        CP_WAIT0();
        __syncthreads();

        const int kn = k0 + BK;
        if (kn < C_) {
            float* Bw = Bsb + (p ^ 1) * BSZ;
            #pragma unroll
            for (int q = 0; q < 8; q++)
                cp_async16(&Bw[brow * SB + bcol0 + q * 32],
                           bptr + (size_t)kn * C_ + q * 32);
            float* Aw = Asb + (p ^ 1) * ASZ;
            #pragma unroll
            for (int q = 0; q < 2; q++)
                cp_async16(&Aw[arow * SA + acol0 + q * 4], asrc + kn + q * 4);
            CP_COMMIT();
        }

        const float* A_ = Asb + p * ASZ;
        const float* B_ = Bsb + p * BSZ;
        #pragma unroll
        for (int kk = 0; kk < BK; kk += 8) {
            unsigned a[2][4];
            #pragma unroll
            for (int mt = 0; mt < 2; mt++) {
                int rb = warp_m * 32 + mt * 16;
                a[mt][0] = __float_as_uint(A_[(rb + grp    ) * SA + kk + qid    ]);
                a[mt][1] = __float_as_uint(A_[(rb + grp + 8) * SA + kk + qid    ]);
                a[mt][2] = __float_as_uint(A_[(rb + grp    ) * SA + kk + qid + 4]);
                a[mt][3] = __float_as_uint(A_[(rb + grp + 8) * SA + kk + qid + 4]);
            }
            unsigned b[8][2];
            #pragma unroll
            for (int nt = 0; nt < 8; nt++) {
                int cb = warp_n * 64 + nt * 8;
                b[nt][0] = __float_as_uint(B_[(kk + qid    ) * SB + cb + grp]);
                b[nt][1] = __float_as_uint(B_[(kk + qid + 4) * SB + cb + grp]);
            }
            #pragma unroll
            for (int mt = 0; mt < 2; mt++)
                #pragma unroll
                for (int nt = 0; nt < 8; nt++)
                    mma_tf32(acc[mt][nt], a[mt][0], a[mt][1], a[mt][2], a[mt][3],
                             b[nt][0], b[nt][1]);
        }
        p ^= 1;
    }

    // ---- Epilogue: bias + spatial scatter ----
    const int tf = w >> 10, wh = (w >> 5) & 31, wc = w & 31;

    #pragma unroll
    for (int nt = 0; nt < 8; nt++) {
        int col = warp_n * 64 + nt * 8 + 2 * qid;
        float b0 = pb[col], b1 = pb[col + 1];
        #pragma unroll
        for (int mt = 0; mt < 2; mt++) {
            #pragma unroll
            for (int half = 0; half < 2; half++) {
                int m  = warp_m * 32 + mt * 16 + grp + half * 8;
                int pi = m >> 3, pj = m & 7;
                float* orow = out + ((size_t)(tf * HH + wh * PS_ + pi) * WW
                                     + wc * PS_ + pj) * C_;
                float2 o = { acc[mt][nt][half * 2 + 0] + b0,
                             acc[mt][nt][half * 2 + 1] + b1 };
                *(float2*)(orow + col) = o;
            }
        }
    }
}

// ---------------------------------------------------------------------------
extern "C" void kernel_launch(void* const* d_in, const int* in_sizes, int n_in,
                              void* d_out, int out_size)
{
    const float* vid  = (const float*)d_in[0];
    const float* mod  = (const float*)d_in[1];
    const float* wq   = (const float*)d_in[2];
    const float* bq   = (const float*)d_in[3];
    const float* wkv  = (const float*)d_in[4];
    const float* bkv  = (const float*)d_in[5];
    const float* pw   = (const float*)d_in[6];
    const float* pb   = (const float*)d_in[7];
    const float* rpt  = (const float*)d_in[8];
    float* out = (float*)d_out;

    cudaFuncSetAttribute(qkv_kernel,  cudaFuncAttributeMaxDynamicSharedMemorySize, SMEM_GEMM);
    cudaFuncSetAttribute(proj_kernel, cudaFuncAttributeMaxDynamicSharedMemorySize, SMEM_GEMM);

    prep_weights<<<512, 256>>>(wq, wkv, pw);

    dim3 g1(3, NWIN);
    qkv_kernel<<<g1, 256, SMEM_GEMM>>>(vid, mod, bq, bkv);

    dim3 g2(NWIN, NH_ / 2);
    attn_kernel<<<g2, 128>>>(rpt);

    proj_kernel<<<NWIN, 256, SMEM_GEMM>>>(pb, out);
}